// round 12
// baseline (speedup 1.0000x reference)
#include <cuda_runtime.h>

// PixCorr: per-row Pearson correlation over [256, 196608] fp32 rows, then
// mean over rows.
//
// R10 structure (best: 61.5us) + two tail optimizations:
//  1. Row kernel calls cudaTriggerProgrammaticLaunchCompletion() at ENTRY,
//     so the PDL-launched mean kernel is fully set up and parked inside
//     cudaGridDependencySynchronize() while the row kernel streams.
//     (Correctness of g_corr is guaranteed by GridDependencySynchronize,
//     which waits for primary completion + memory flush regardless.)
//  2. Mean kernel is a single warp (32 threads x 8 values, shfl-only
//     reduce): no barrier, no shared memory after the dependency release.

#define NROWS   256
#define D_ELEMS 196608          // 3*256*256
#define NVEC    (D_ELEMS / 4)   // 49152 float4 per row
#define THREADS 1024
#define EPS     1e-6f

__device__ float g_corr[NROWS];

__device__ __forceinline__ float warp_sum(float v) {
    v += __shfl_xor_sync(0xFFFFFFFFu, v, 16);
    v += __shfl_xor_sync(0xFFFFFFFFu, v, 8);
    v += __shfl_xor_sync(0xFFFFFFFFu, v, 4);
    v += __shfl_xor_sync(0xFFFFFFFFu, v, 2);
    v += __shfl_xor_sync(0xFFFFFFFFu, v, 1);
    return v;
}

__global__ __launch_bounds__(THREADS, 1)
void pixcorr_row_kernel(const float* __restrict__ preds,
                        const float* __restrict__ targets) {
    // Fire the programmatic launch-completion trigger immediately: the
    // dependent mean kernel may launch now and park in
    // cudaGridDependencySynchronize() until this grid completes.
    cudaTriggerProgrammaticLaunchCompletion();

    const int row = blockIdx.x;
    const float4* __restrict__ z4 =
        reinterpret_cast<const float4*>(targets + (size_t)row * D_ELEMS);
    const float4* __restrict__ b4 =
        reinterpret_cast<const float4*>(preds + (size_t)row * D_ELEMS);

    float sz = 0.f, sb = 0.f, szz = 0.f, sbb = 0.f, szb = 0.f;

    // 48 iterations per thread, fully coalesced plain cached float4 loads.
    #pragma unroll 4
    for (int i = threadIdx.x; i < NVEC; i += THREADS) {
        float4 zv = z4[i];
        float4 bv = b4[i];
        sz  += (zv.x + zv.y) + (zv.z + zv.w);
        sb  += (bv.x + bv.y) + (bv.z + bv.w);
        szz  = fmaf(zv.x, zv.x, fmaf(zv.y, zv.y, fmaf(zv.z, zv.z, fmaf(zv.w, zv.w, szz))));
        sbb  = fmaf(bv.x, bv.x, fmaf(bv.y, bv.y, fmaf(bv.z, bv.z, fmaf(bv.w, bv.w, sbb))));
        szb  = fmaf(zv.x, bv.x, fmaf(zv.y, bv.y, fmaf(zv.z, bv.z, fmaf(zv.w, bv.w, szb))));
    }

    sz  = warp_sum(sz);
    sb  = warp_sum(sb);
    szz = warp_sum(szz);
    sbb = warp_sum(sbb);
    szb = warp_sum(szb);

    __shared__ float sh[5][THREADS / 32];
    const int lane = threadIdx.x & 31;
    const int wid  = threadIdx.x >> 5;
    if (lane == 0) {
        sh[0][wid] = sz;  sh[1][wid] = sb;
        sh[2][wid] = szz; sh[3][wid] = sbb; sh[4][wid] = szb;
    }
    __syncthreads();

    if (threadIdx.x < 32) {
        float a0 = warp_sum(sh[0][lane]);
        float a1 = warp_sum(sh[1][lane]);
        float a2 = warp_sum(sh[2][lane]);
        float a3 = warp_sum(sh[3][lane]);
        float a4 = warp_sum(sh[4][lane]);
        if (lane == 0) {
            const float invD = 1.0f / (float)D_ELEMS;
            float cov = a4 - a0 * a1 * invD;
            float vz  = fmaxf(a2 - a0 * a0 * invD, 0.f);
            float vb  = fmaxf(a3 - a1 * a1 * invD, 0.f);
            g_corr[row] = cov / (sqrtf(vz) * sqrtf(vb) + EPS);
        }
    }
}

__global__ void pixcorr_mean_kernel(float* __restrict__ out) {
    // Wait for the primary grid's completion + memory flush.
    cudaGridDependencySynchronize();

    // Single warp: each lane sums 8 of the 256 corrs, then shfl-reduce.
    const int lane = threadIdx.x;  // 0..31
    float s = 0.f;
    #pragma unroll
    for (int i = 0; i < NROWS / 32; i++)
        s += g_corr[lane + i * 32];
    s = warp_sum(s);
    if (lane == 0)
        out[0] = s * (1.0f / (float)NROWS);
}

extern "C" void kernel_launch(void* const* d_in, const int* in_sizes, int n_in,
                              void* d_out, int out_size) {
    const float* preds   = (const float*)d_in[0];
    const float* targets = (const float*)d_in[1];
    float* out = (float*)d_out;

    pixcorr_row_kernel<<<NROWS, THREADS>>>(preds, targets);

    // PDL launch: the mean kernel's setup overlaps the row kernel.
    cudaLaunchConfig_t cfg = {};
    cfg.gridDim  = dim3(1, 1, 1);
    cfg.blockDim = dim3(32, 1, 1);
    cfg.dynamicSmemBytes = 0;
    cfg.stream = 0;  // same stream as the row kernel
    cudaLaunchAttribute attr[1];
    attr[0].id = cudaLaunchAttributeProgrammaticStreamSerialization;
    attr[0].val.programmaticStreamSerializationAllowed = 1;
    cfg.attrs = attr;
    cfg.numAttrs = 1;

    cudaError_t e = cudaLaunchKernelEx(&cfg, pixcorr_mean_kernel, out);
    if (e != cudaSuccess) {
        // Fallback: plain serialized launch (identical semantics).
        pixcorr_mean_kernel<<<1, 32>>>(out);
    }
}